// round 1
// baseline (speedup 1.0000x reference)
#include <cuda_runtime.h>

#define CH 256
#define NMAX 200000
#define KOFF 27
#define PATHS 4

// Scratch (device globals: no allocation allowed in kernel_launch)
__device__ float g_H[(size_t)NMAX * CH];     // lifted features [N,256] (path p in cols p*64..)
__device__ float g_A[(size_t)NMAX * CH];     // conv accumulator [N,256]
__device__ float g_sum[CH];
__device__ float g_sumsq[CH];
__device__ float g_scale[CH];
__device__ float g_shift[CH];

// ---------------------------------------------------------------------------
// Zero conv accumulator + BN partials
__global__ void zero_init(size_t total4) {
    size_t i = (size_t)blockIdx.x * blockDim.x + threadIdx.x;
    if (i < total4) ((float4*)g_A)[i] = make_float4(0.f, 0.f, 0.f, 0.f);
    if (i < CH) { g_sum[i] = 0.f; g_sumsq[i] = 0.f; }
}

// ---------------------------------------------------------------------------
// H = x @ Wl_cat + bl   (Wl: [P,256,64]; col tile = one path, so no repack)
// Tile: 128 rows x 64 cols, BK=32, 256 threads, 8x4 outputs/thread.
__global__ __launch_bounds__(256) void gemm_h(const float* __restrict__ x,
                                              const float* __restrict__ Wl,
                                              const float* __restrict__ bl,
                                              int n) {
    __shared__ float As[32][132];   // [k][m], pad 132 keeps float4 reads aligned
    __shared__ float Bs[32][64];    // [k][d]
    int p = blockIdx.x;
    int rowBase = blockIdx.y * 128;
    int tid = threadIdx.x;
    int tx = tid & 15, ty = tid >> 4;
    float acc[8][4];
#pragma unroll
    for (int r = 0; r < 8; r++)
#pragma unroll
        for (int c = 0; c < 4; c++) acc[r][c] = 0.f;

    for (int kt = 0; kt < 8; kt++) {
#pragma unroll
        for (int i = 0; i < 4; i++) {           // A tile 128x32
            int id = tid + i * 256;
            int row = id >> 3, kq = id & 7;
            int gr = rowBase + row;
            float4 v = make_float4(0.f, 0.f, 0.f, 0.f);
            if (gr < n) v = *(const float4*)&x[(size_t)gr * CH + kt * 32 + kq * 4];
            As[kq * 4 + 0][row] = v.x; As[kq * 4 + 1][row] = v.y;
            As[kq * 4 + 2][row] = v.z; As[kq * 4 + 3][row] = v.w;
        }
#pragma unroll
        for (int i = 0; i < 2; i++) {           // B tile 32x64
            int id = tid + i * 256;
            int kk = id >> 4, dq = id & 15;
            *(float4*)&Bs[kk][dq * 4] =
                *(const float4*)&Wl[(size_t)(p * 256 + kt * 32 + kk) * 64 + dq * 4];
        }
        __syncthreads();
#pragma unroll
        for (int kc = 0; kc < 32; kc++) {
            float4 b = *(const float4*)&Bs[kc][tx * 4];
            float4 a0 = *(const float4*)&As[kc][ty * 8];
            float4 a1 = *(const float4*)&As[kc][ty * 8 + 4];
            float ar[8] = {a0.x, a0.y, a0.z, a0.w, a1.x, a1.y, a1.z, a1.w};
            float bc[4] = {b.x, b.y, b.z, b.w};
#pragma unroll
            for (int r = 0; r < 8; r++)
#pragma unroll
                for (int c = 0; c < 4; c++) acc[r][c] += ar[r] * bc[c];
        }
        __syncthreads();
    }
    float4 bb = *(const float4*)&bl[p * 64 + tx * 4];
#pragma unroll
    for (int r = 0; r < 8; r++) {
        int gr = rowBase + ty * 8 + r;
        if (gr < n) {
            float4 o = make_float4(acc[r][0] + bb.x, acc[r][1] + bb.y,
                                   acc[r][2] + bb.z, acc[r][3] + bb.w);
            *(float4*)&g_H[(size_t)gr * CH + p * 64 + tx * 4] = o;
        }
    }
}

// ---------------------------------------------------------------------------
// Sparse conv: per (p,k) tile of 64 pairs, gather H rows, 64x64x64 GEMM,
// scatter-add into g_A. Valid pairs are a prefix -> block early-exit.
__global__ __launch_bounds__(256) void conv_scatter(const float* __restrict__ Wc,
                                                    const int* __restrict__ in_idx,
                                                    const int* __restrict__ out_idx,
                                                    int n, int M) {
    __shared__ float Gs[64][68];    // [c][m], stride 68 keeps float4 reads aligned
    __shared__ float Ws[64][64];    // [c][d]
    __shared__ int Os[64];
    int p = blockIdx.z, k = blockIdx.y;
    size_t base = (size_t)(p * KOFF + k) * M + (size_t)blockIdx.x * 64;
    const int* ii = in_idx + base;
    if (__ldg(ii) >= n) return;     // whole tile is sentinel padding
    int rem = M - blockIdx.x * 64; if (rem > 64) rem = 64;
    int tid = threadIdx.x;

    const float* Wpk = Wc + (size_t)(p * KOFF + k) * 4096;
#pragma unroll
    for (int i = 0; i < 4; i++) {
        int id = tid + i * 256;
        int c = id >> 4, dq = id & 15;
        *(float4*)&Ws[c][dq * 4] = *(const float4*)&Wpk[c * 64 + dq * 4];
    }
    int m = tid & 63, cg = tid >> 6;
    int jm = (m < rem) ? __ldg(&ii[m]) : n;
    bool valid = jm < n;
    if (cg == 0) Os[m] = valid ? __ldg(&out_idx[base + m]) : -1;
    if (valid) {
        const float* hp = &g_H[(size_t)jm * CH + p * 64 + cg * 16];
#pragma unroll
        for (int q = 0; q < 4; q++) {
            float4 v = *(const float4*)&hp[q * 4];
            Gs[cg * 16 + q * 4 + 0][m] = v.x; Gs[cg * 16 + q * 4 + 1][m] = v.y;
            Gs[cg * 16 + q * 4 + 2][m] = v.z; Gs[cg * 16 + q * 4 + 3][m] = v.w;
        }
    } else {
#pragma unroll
        for (int q = 0; q < 4; q++) {
            Gs[cg * 16 + q * 4 + 0][m] = 0.f; Gs[cg * 16 + q * 4 + 1][m] = 0.f;
            Gs[cg * 16 + q * 4 + 2][m] = 0.f; Gs[cg * 16 + q * 4 + 3][m] = 0.f;
        }
    }
    __syncthreads();

    int tx = tid & 15, ty = tid >> 4;
    float acc[4][4];
#pragma unroll
    for (int r = 0; r < 4; r++)
#pragma unroll
        for (int c = 0; c < 4; c++) acc[r][c] = 0.f;
#pragma unroll
    for (int kc = 0; kc < 64; kc++) {
        float4 g = *(const float4*)&Gs[kc][ty * 4];
        float4 w = *(const float4*)&Ws[kc][tx * 4];
        acc[0][0] += g.x * w.x; acc[0][1] += g.x * w.y; acc[0][2] += g.x * w.z; acc[0][3] += g.x * w.w;
        acc[1][0] += g.y * w.x; acc[1][1] += g.y * w.y; acc[1][2] += g.y * w.z; acc[1][3] += g.y * w.w;
        acc[2][0] += g.z * w.x; acc[2][1] += g.z * w.y; acc[2][2] += g.z * w.z; acc[2][3] += g.z * w.w;
        acc[3][0] += g.w * w.x; acc[3][1] += g.w * w.y; acc[3][2] += g.w * w.z; acc[3][3] += g.w * w.w;
    }
#pragma unroll
    for (int r = 0; r < 4; r++) {
        int o = Os[ty * 4 + r];
        if (o >= 0) {
            float* dst = &g_A[(size_t)o * CH + p * 64 + tx * 4];
            atomicAdd(dst + 0, acc[r][0]);
            atomicAdd(dst + 1, acc[r][1]);
            atomicAdd(dst + 2, acc[r][2]);
            atomicAdd(dst + 3, acc[r][3]);
        }
    }
}

// ---------------------------------------------------------------------------
// Per-channel sum / sumsq over all n rows (one streaming pass over g_A)
__global__ __launch_bounds__(256) void bn_stats(int n) {
    int c = threadIdx.x;
    float s = 0.f, s2 = 0.f;
    for (int r = blockIdx.x; r < n; r += gridDim.x) {
        float v = g_A[(size_t)r * CH + c];
        s += v; s2 += v * v;
    }
    atomicAdd(&g_sum[c], s);
    atomicAdd(&g_sumsq[c], s2);
}

__global__ void bn_finalize(const float* __restrict__ gamma,
                            const float* __restrict__ beta, int n) {
    int j = threadIdx.x;
    float inv = 1.f / (float)n;
    float mu = g_sum[j] * inv;
    float var = g_sumsq[j] * inv - mu * mu;
    float sc = gamma[j] * rsqrtf(var + 1e-5f);
    g_scale[j] = sc;
    g_shift[j] = beta[j] - mu * sc;
}

// ---------------------------------------------------------------------------
// out = relu(bn(A)) @ W2 + b2 + x   (norm+relu fused into A-load)
__global__ __launch_bounds__(256) void gemm_out(const float* __restrict__ W2,
                                                const float* __restrict__ b2,
                                                const float* __restrict__ x,
                                                float* __restrict__ out, int n) {
    __shared__ float As[32][132];
    __shared__ float Bs[32][64];
    int colBase = blockIdx.x * 64;
    int rowBase = blockIdx.y * 128;
    int tid = threadIdx.x;
    int tx = tid & 15, ty = tid >> 4;
    float acc[8][4];
#pragma unroll
    for (int r = 0; r < 8; r++)
#pragma unroll
        for (int c = 0; c < 4; c++) acc[r][c] = 0.f;

    for (int kt = 0; kt < 8; kt++) {
#pragma unroll
        for (int i = 0; i < 4; i++) {
            int id = tid + i * 256;
            int row = id >> 3, kq = id & 7;
            int gr = rowBase + row;
            float4 v = make_float4(0.f, 0.f, 0.f, 0.f);
            if (gr < n) {
                v = *(const float4*)&g_A[(size_t)gr * CH + kt * 32 + kq * 4];
                int c0 = kt * 32 + kq * 4;
                v.x = fmaxf(v.x * g_scale[c0 + 0] + g_shift[c0 + 0], 0.f);
                v.y = fmaxf(v.y * g_scale[c0 + 1] + g_shift[c0 + 1], 0.f);
                v.z = fmaxf(v.z * g_scale[c0 + 2] + g_shift[c0 + 2], 0.f);
                v.w = fmaxf(v.w * g_scale[c0 + 3] + g_shift[c0 + 3], 0.f);
            }
            As[kq * 4 + 0][row] = v.x; As[kq * 4 + 1][row] = v.y;
            As[kq * 4 + 2][row] = v.z; As[kq * 4 + 3][row] = v.w;
        }
#pragma unroll
        for (int i = 0; i < 2; i++) {
            int id = tid + i * 256;
            int kk = id >> 4, dq = id & 15;
            *(float4*)&Bs[kk][dq * 4] =
                *(const float4*)&W2[(size_t)(kt * 32 + kk) * CH + colBase + dq * 4];
        }
        __syncthreads();
#pragma unroll
        for (int kc = 0; kc < 32; kc++) {
            float4 b = *(const float4*)&Bs[kc][tx * 4];
            float4 a0 = *(const float4*)&As[kc][ty * 8];
            float4 a1 = *(const float4*)&As[kc][ty * 8 + 4];
            float ar[8] = {a0.x, a0.y, a0.z, a0.w, a1.x, a1.y, a1.z, a1.w};
            float bc[4] = {b.x, b.y, b.z, b.w};
#pragma unroll
            for (int r = 0; r < 8; r++)
#pragma unroll
                for (int c = 0; c < 4; c++) acc[r][c] += ar[r] * bc[c];
        }
        __syncthreads();
    }
    float4 bb = *(const float4*)&b2[colBase + tx * 4];
#pragma unroll
    for (int r = 0; r < 8; r++) {
        int gr = rowBase + ty * 8 + r;
        if (gr < n) {
            float4 xr = *(const float4*)&x[(size_t)gr * CH + colBase + tx * 4];
            float4 o = make_float4(acc[r][0] + bb.x + xr.x, acc[r][1] + bb.y + xr.y,
                                   acc[r][2] + bb.z + xr.z, acc[r][3] + bb.w + xr.w);
            *(float4*)&out[(size_t)gr * CH + colBase + tx * 4] = o;
        }
    }
}

// ---------------------------------------------------------------------------
extern "C" void kernel_launch(void* const* d_in, const int* in_sizes, int n_in,
                              void* d_out, int out_size) {
    const float* x     = (const float*)d_in[0];
    const float* Wl    = (const float*)d_in[1];
    const float* bl    = (const float*)d_in[2];
    const float* Wc    = (const float*)d_in[3];
    const float* gamma = (const float*)d_in[4];
    const float* beta  = (const float*)d_in[5];
    const float* W2    = (const float*)d_in[6];
    const float* b2    = (const float*)d_in[7];
    const int* in_idx  = (const int*)d_in[8];
    const int* out_idx = (const int*)d_in[9];
    float* out = (float*)d_out;

    int n = in_sizes[0] / CH;                 // 200000
    int M = in_sizes[8] / (PATHS * KOFF);     // max pairs per (p,k)

    size_t total4 = (size_t)n * CH / 4;
    int zb = (int)((total4 + 255) / 256);
    zero_init<<<zb, 256>>>(total4);
    gemm_h<<<dim3(PATHS, (n + 127) / 128), 256>>>(x, Wl, bl, n);
    conv_scatter<<<dim3((M + 63) / 64, KOFF, PATHS), 256>>>(Wc, in_idx, out_idx, n, M);
    bn_stats<<<2048, 256>>>(n);
    bn_finalize<<<1, 256>>>(gamma, beta, n);
    gemm_out<<<dim3(PATHS, (n + 127) / 128), 256>>>(W2, b2, x, out, n);
}

// round 2
// speedup vs baseline: 1.6880x; 1.6880x over previous
#include <cuda_runtime.h>
#include <cstdint>

#define CH 256
#define NMAX 200000
#define KOFF 27
#define PATHS 4

// Scratch (device globals: no allocation allowed in kernel_launch)
__device__ float g_H[(size_t)NMAX * CH];     // lifted features [N,256] (path p in cols p*64..)
__device__ float g_A[(size_t)NMAX * CH];     // conv accumulator [N,256]
__device__ float g_sum[CH];
__device__ float g_sumsq[CH];
__device__ float g_scale[CH];
__device__ float g_shift[CH];

// ---------------------------------------------------------------------------
__device__ __forceinline__ float to_tf32(float f) {
    uint32_t u;
    asm("cvt.rna.tf32.f32 %0, %1;" : "=r"(u) : "f"(f));
    return __uint_as_float(u);
}

__device__ __forceinline__ void mma_tf32(float c[4], uint32_t a0, uint32_t a1,
                                         uint32_t a2, uint32_t a3,
                                         uint32_t b0, uint32_t b1) {
    asm volatile(
        "mma.sync.aligned.m16n8k8.row.col.f32.tf32.tf32.f32 "
        "{%0,%1,%2,%3}, {%4,%5,%6,%7}, {%8,%9}, {%0,%1,%2,%3};\n"
        : "+f"(c[0]), "+f"(c[1]), "+f"(c[2]), "+f"(c[3])
        : "r"(a0), "r"(a1), "r"(a2), "r"(a3), "r"(b0), "r"(b1));
}

// ---------------------------------------------------------------------------
// Zero conv accumulator + BN partials
__global__ void zero_init(size_t total4) {
    size_t i = (size_t)blockIdx.x * blockDim.x + threadIdx.x;
    if (i < total4) ((float4*)g_A)[i] = make_float4(0.f, 0.f, 0.f, 0.f);
    if (i < CH) { g_sum[i] = 0.f; g_sumsq[i] = 0.f; }
}

// ---------------------------------------------------------------------------
// H = x @ Wl_cat + bl  (tf32 mma; tile 128x64, BK=32, 8 warps in 4x2)
__global__ __launch_bounds__(256) void gemm_h(const float* __restrict__ x,
                                              const float* __restrict__ Wl,
                                              const float* __restrict__ bl,
                                              int n) {
    __shared__ float As[128][36];   // [m][k], stride 36: conflict-free frag loads
    __shared__ float Bs[32][72];    // [k][n], stride 72: conflict-free frag loads
    int p = blockIdx.x;
    int rowBase = blockIdx.y * 128;
    int tid = threadIdx.x;
    int warpId = tid >> 5, lane = tid & 31;
    int grp = lane >> 2, qp = lane & 3;
    int wm = (warpId & 3) * 32;     // warp m-offset (4 warps over 128)
    int wn = (warpId >> 2) * 32;    // warp n-offset (2 warps over 64)

    float acc[2][4][4];
#pragma unroll
    for (int mt = 0; mt < 2; mt++)
#pragma unroll
        for (int nt = 0; nt < 4; nt++)
#pragma unroll
            for (int r = 0; r < 4; r++) acc[mt][nt][r] = 0.f;

    for (int kt = 0; kt < 8; kt++) {
#pragma unroll
        for (int i = 0; i < 4; i++) {          // A tile 128x32
            int id = tid + i * 256;
            int row = id >> 3, kq = id & 7;
            int gr = rowBase + row;
            float4 v = make_float4(0.f, 0.f, 0.f, 0.f);
            if (gr < n) v = *(const float4*)&x[(size_t)gr * CH + kt * 32 + kq * 4];
            v.x = to_tf32(v.x); v.y = to_tf32(v.y);
            v.z = to_tf32(v.z); v.w = to_tf32(v.w);
            *(float4*)&As[row][kq * 4] = v;
        }
#pragma unroll
        for (int i = 0; i < 2; i++) {          // B tile 32x64
            int id = tid + i * 256;
            int kk = id >> 4, dq = id & 15;
            float4 v = *(const float4*)&Wl[(size_t)(p * 256 + kt * 32 + kk) * 64 + dq * 4];
            v.x = to_tf32(v.x); v.y = to_tf32(v.y);
            v.z = to_tf32(v.z); v.w = to_tf32(v.w);
            *(float4*)&Bs[kk][dq * 4] = v;
        }
        __syncthreads();
#pragma unroll
        for (int c8 = 0; c8 < 4; c8++) {
            int kk0 = c8 * 8;
            uint32_t af[2][4], bf[4][2];
#pragma unroll
            for (int mt = 0; mt < 2; mt++) {
                int r0 = wm + mt * 16 + grp;
                af[mt][0] = __float_as_uint(As[r0][kk0 + qp]);
                af[mt][1] = __float_as_uint(As[r0 + 8][kk0 + qp]);
                af[mt][2] = __float_as_uint(As[r0][kk0 + qp + 4]);
                af[mt][3] = __float_as_uint(As[r0 + 8][kk0 + qp + 4]);
            }
#pragma unroll
            for (int nt = 0; nt < 4; nt++) {
                int c0 = wn + nt * 8 + grp;
                bf[nt][0] = __float_as_uint(Bs[kk0 + qp][c0]);
                bf[nt][1] = __float_as_uint(Bs[kk0 + qp + 4][c0]);
            }
#pragma unroll
            for (int mt = 0; mt < 2; mt++)
#pragma unroll
                for (int nt = 0; nt < 4; nt++)
                    mma_tf32(acc[mt][nt], af[mt][0], af[mt][1], af[mt][2], af[mt][3],
                             bf[nt][0], bf[nt][1]);
        }
        __syncthreads();
    }
#pragma unroll
    for (int mt = 0; mt < 2; mt++) {
#pragma unroll
        for (int nt = 0; nt < 4; nt++) {
            int col = wn + nt * 8 + qp * 2;
            float b0 = bl[p * 64 + col], b1 = bl[p * 64 + col + 1];
            int gr0 = rowBase + wm + mt * 16 + grp;
            if (gr0 < n) {
                float2 o = make_float2(acc[mt][nt][0] + b0, acc[mt][nt][1] + b1);
                *(float2*)&g_H[(size_t)gr0 * CH + p * 64 + col] = o;
            }
            int gr1 = gr0 + 8;
            if (gr1 < n) {
                float2 o = make_float2(acc[mt][nt][2] + b0, acc[mt][nt][3] + b1);
                *(float2*)&g_H[(size_t)gr1 * CH + p * 64 + col] = o;
            }
        }
    }
}

// ---------------------------------------------------------------------------
// Sparse conv: tile of 128 pairs -> gather -> 128x64x64 tf32 mma -> scatter-add
__global__ __launch_bounds__(256) void conv_scatter(const float* __restrict__ Wc,
                                                    const int* __restrict__ in_idx,
                                                    const int* __restrict__ out_idx,
                                                    int n, int M) {
    __shared__ float Gs[128][68];   // [pair][c]
    __shared__ float Ws[64][72];    // [c][d]
    __shared__ int Os[128];
    int p = blockIdx.z, k = blockIdx.y;
    size_t base = (size_t)(p * KOFF + k) * M + (size_t)blockIdx.x * 128;
    const int* ii = in_idx + base;
    if (__ldg(ii) >= n) return;     // whole tile is sentinel padding
    int rem = M - blockIdx.x * 128; if (rem > 128) rem = 128;
    int tid = threadIdx.x;

    const float* Wpk = Wc + (size_t)(p * KOFF + k) * 4096;
#pragma unroll
    for (int i = 0; i < 4; i++) {
        int id = tid + i * 256;
        int c = id >> 4, dq = id & 15;
        float4 v = *(const float4*)&Wpk[c * 64 + dq * 4];
        v.x = to_tf32(v.x); v.y = to_tf32(v.y);
        v.z = to_tf32(v.z); v.w = to_tf32(v.w);
        *(float4*)&Ws[c][dq * 4] = v;
    }
    {
        int m = tid >> 1, half = tid & 1;
        int jm = (m < rem) ? __ldg(&ii[m]) : n;
        bool valid = jm < n;
        if (half == 0) Os[m] = valid ? __ldg(&out_idx[base + m]) : -1;
        if (valid) {
            const float* hp = &g_H[(size_t)jm * CH + p * 64 + half * 32];
#pragma unroll
            for (int q = 0; q < 8; q++) {
                float4 v = *(const float4*)&hp[q * 4];
                v.x = to_tf32(v.x); v.y = to_tf32(v.y);
                v.z = to_tf32(v.z); v.w = to_tf32(v.w);
                *(float4*)&Gs[m][half * 32 + q * 4] = v;
            }
        } else {
#pragma unroll
            for (int q = 0; q < 8; q++)
                *(float4*)&Gs[m][half * 32 + q * 4] = make_float4(0.f, 0.f, 0.f, 0.f);
        }
    }
    __syncthreads();

    int warpId = tid >> 5, lane = tid & 31;
    int grp = lane >> 2, qp = lane & 3;
    int wm = (warpId & 3) * 32;
    int wn = (warpId >> 2) * 32;
    float acc[2][4][4];
#pragma unroll
    for (int mt = 0; mt < 2; mt++)
#pragma unroll
        for (int nt = 0; nt < 4; nt++)
#pragma unroll
            for (int r = 0; r < 4; r++) acc[mt][nt][r] = 0.f;

#pragma unroll
    for (int c8 = 0; c8 < 8; c8++) {
        int kk0 = c8 * 8;
        uint32_t af[2][4], bf[4][2];
#pragma unroll
        for (int mt = 0; mt < 2; mt++) {
            int r0 = wm + mt * 16 + grp;
            af[mt][0] = __float_as_uint(Gs[r0][kk0 + qp]);
            af[mt][1] = __float_as_uint(Gs[r0 + 8][kk0 + qp]);
            af[mt][2] = __float_as_uint(Gs[r0][kk0 + qp + 4]);
            af[mt][3] = __float_as_uint(Gs[r0 + 8][kk0 + qp + 4]);
        }
#pragma unroll
        for (int nt = 0; nt < 4; nt++) {
            int c0 = wn + nt * 8 + grp;
            bf[nt][0] = __float_as_uint(Ws[kk0 + qp][c0]);
            bf[nt][1] = __float_as_uint(Ws[kk0 + qp + 4][c0]);
        }
#pragma unroll
        for (int mt = 0; mt < 2; mt++)
#pragma unroll
            for (int nt = 0; nt < 4; nt++)
                mma_tf32(acc[mt][nt], af[mt][0], af[mt][1], af[mt][2], af[mt][3],
                         bf[nt][0], bf[nt][1]);
    }

#pragma unroll
    for (int mt = 0; mt < 2; mt++) {
        int r0 = wm + mt * 16 + grp;
        int o0 = Os[r0], o1 = Os[r0 + 8];
#pragma unroll
        for (int nt = 0; nt < 4; nt++) {
            int col = p * 64 + wn + nt * 8 + qp * 2;
            if (o0 >= 0) {
                atomicAdd(&g_A[(size_t)o0 * CH + col], acc[mt][nt][0]);
                atomicAdd(&g_A[(size_t)o0 * CH + col + 1], acc[mt][nt][1]);
            }
            if (o1 >= 0) {
                atomicAdd(&g_A[(size_t)o1 * CH + col], acc[mt][nt][2]);
                atomicAdd(&g_A[(size_t)o1 * CH + col + 1], acc[mt][nt][3]);
            }
        }
    }
}

// ---------------------------------------------------------------------------
// Per-channel sum / sumsq: float4 per thread, 4 rows in flight, block reduce
__global__ __launch_bounds__(256) void bn_stats(int n) {
    __shared__ float4 rs[4][64], rq[4][64];
    int tid = threadIdx.x;
    int cq = tid & 63;              // channel quad (float4)
    int rl = tid >> 6;              // row lane 0..3
    float4 s = make_float4(0.f, 0.f, 0.f, 0.f);
    float4 s2 = make_float4(0.f, 0.f, 0.f, 0.f);
#pragma unroll 4
    for (int r = blockIdx.x * 4 + rl; r < n; r += gridDim.x * 4) {
        float4 v = *(const float4*)&g_A[(size_t)r * CH + cq * 4];
        s.x += v.x; s.y += v.y; s.z += v.z; s.w += v.w;
        s2.x += v.x * v.x; s2.y += v.y * v.y; s2.z += v.z * v.z; s2.w += v.w * v.w;
    }
    rs[rl][cq] = s; rq[rl][cq] = s2;
    __syncthreads();
    if (rl == 0) {
#pragma unroll
        for (int i = 1; i < 4; i++) {
            float4 a = rs[i][cq], b = rq[i][cq];
            s.x += a.x; s.y += a.y; s.z += a.z; s.w += a.w;
            s2.x += b.x; s2.y += b.y; s2.z += b.z; s2.w += b.w;
        }
        int c = cq * 4;
        atomicAdd(&g_sum[c + 0], s.x);  atomicAdd(&g_sum[c + 1], s.y);
        atomicAdd(&g_sum[c + 2], s.z);  atomicAdd(&g_sum[c + 3], s.w);
        atomicAdd(&g_sumsq[c + 0], s2.x); atomicAdd(&g_sumsq[c + 1], s2.y);
        atomicAdd(&g_sumsq[c + 2], s2.z); atomicAdd(&g_sumsq[c + 3], s2.w);
    }
}

__global__ void bn_finalize(const float* __restrict__ gamma,
                            const float* __restrict__ beta, int n) {
    int j = threadIdx.x;
    float inv = 1.f / (float)n;
    float mu = g_sum[j] * inv;
    float var = g_sumsq[j] * inv - mu * mu;
    float sc = gamma[j] * rsqrtf(var + 1e-5f);
    g_scale[j] = sc;
    g_shift[j] = beta[j] - mu * sc;
}

// ---------------------------------------------------------------------------
// out = relu(bn(A)) @ W2 + b2 + x  (tf32 mma; bn+relu fused into A staging)
__global__ __launch_bounds__(256) void gemm_out(const float* __restrict__ W2,
                                                const float* __restrict__ b2,
                                                const float* __restrict__ x,
                                                float* __restrict__ out, int n) {
    __shared__ float As[128][36];
    __shared__ float Bs[32][72];
    int colBase = blockIdx.x * 64;
    int rowBase = blockIdx.y * 128;
    int tid = threadIdx.x;
    int warpId = tid >> 5, lane = tid & 31;
    int grp = lane >> 2, qp = lane & 3;
    int wm = (warpId & 3) * 32;
    int wn = (warpId >> 2) * 32;

    float acc[2][4][4];
#pragma unroll
    for (int mt = 0; mt < 2; mt++)
#pragma unroll
        for (int nt = 0; nt < 4; nt++)
#pragma unroll
            for (int r = 0; r < 4; r++) acc[mt][nt][r] = 0.f;

    for (int kt = 0; kt < 8; kt++) {
#pragma unroll
        for (int i = 0; i < 4; i++) {
            int id = tid + i * 256;
            int row = id >> 3, kq = id & 7;
            int gr = rowBase + row;
            float4 v = make_float4(0.f, 0.f, 0.f, 0.f);
            if (gr < n) {
                v = *(const float4*)&g_A[(size_t)gr * CH + kt * 32 + kq * 4];
                int c0 = kt * 32 + kq * 4;
                v.x = fmaxf(v.x * g_scale[c0 + 0] + g_shift[c0 + 0], 0.f);
                v.y = fmaxf(v.y * g_scale[c0 + 1] + g_shift[c0 + 1], 0.f);
                v.z = fmaxf(v.z * g_scale[c0 + 2] + g_shift[c0 + 2], 0.f);
                v.w = fmaxf(v.w * g_scale[c0 + 3] + g_shift[c0 + 3], 0.f);
                v.x = to_tf32(v.x); v.y = to_tf32(v.y);
                v.z = to_tf32(v.z); v.w = to_tf32(v.w);
            }
            *(float4*)&As[row][kq * 4] = v;
        }
#pragma unroll
        for (int i = 0; i < 2; i++) {
            int id = tid + i * 256;
            int kk = id >> 4, dq = id & 15;
            float4 v = *(const float4*)&W2[(size_t)(kt * 32 + kk) * CH + colBase + dq * 4];
            v.x = to_tf32(v.x); v.y = to_tf32(v.y);
            v.z = to_tf32(v.z); v.w = to_tf32(v.w);
            *(float4*)&Bs[kk][dq * 4] = v;
        }
        __syncthreads();
#pragma unroll
        for (int c8 = 0; c8 < 4; c8++) {
            int kk0 = c8 * 8;
            uint32_t af[2][4], bf[4][2];
#pragma unroll
            for (int mt = 0; mt < 2; mt++) {
                int r0 = wm + mt * 16 + grp;
                af[mt][0] = __float_as_uint(As[r0][kk0 + qp]);
                af[mt][1] = __float_as_uint(As[r0 + 8][kk0 + qp]);
                af[mt][2] = __float_as_uint(As[r0][kk0 + qp + 4]);
                af[mt][3] = __float_as_uint(As[r0 + 8][kk0 + qp + 4]);
            }
#pragma unroll
            for (int nt = 0; nt < 4; nt++) {
                int c0 = wn + nt * 8 + grp;
                bf[nt][0] = __float_as_uint(Bs[kk0 + qp][c0]);
                bf[nt][1] = __float_as_uint(Bs[kk0 + qp + 4][c0]);
            }
#pragma unroll
            for (int mt = 0; mt < 2; mt++)
#pragma unroll
                for (int nt = 0; nt < 4; nt++)
                    mma_tf32(acc[mt][nt], af[mt][0], af[mt][1], af[mt][2], af[mt][3],
                             bf[nt][0], bf[nt][1]);
        }
        __syncthreads();
    }
#pragma unroll
    for (int mt = 0; mt < 2; mt++) {
#pragma unroll
        for (int nt = 0; nt < 4; nt++) {
            int col = colBase + wn + nt * 8 + qp * 2;
            float b0 = b2[col], b1 = b2[col + 1];
            int gr0 = rowBase + wm + mt * 16 + grp;
            if (gr0 < n) {
                float2 xr = *(const float2*)&x[(size_t)gr0 * CH + col];
                float2 o = make_float2(acc[mt][nt][0] + b0 + xr.x,
                                       acc[mt][nt][1] + b1 + xr.y);
                *(float2*)&out[(size_t)gr0 * CH + col] = o;
            }
            int gr1 = gr0 + 8;
            if (gr1 < n) {
                float2 xr = *(const float2*)&x[(size_t)gr1 * CH + col];
                float2 o = make_float2(acc[mt][nt][2] + b0 + xr.x,
                                       acc[mt][nt][3] + b1 + xr.y);
                *(float2*)&out[(size_t)gr1 * CH + col] = o;
            }
        }
    }
}

// ---------------------------------------------------------------------------
extern "C" void kernel_launch(void* const* d_in, const int* in_sizes, int n_in,
                              void* d_out, int out_size) {
    const float* x     = (const float*)d_in[0];
    const float* Wl    = (const float*)d_in[1];
    const float* bl    = (const float*)d_in[2];
    const float* Wc    = (const float*)d_in[3];
    const float* gamma = (const float*)d_in[4];
    const float* beta  = (const float*)d_in[5];
    const float* W2    = (const float*)d_in[6];
    const float* b2    = (const float*)d_in[7];
    const int* in_idx  = (const int*)d_in[8];
    const int* out_idx = (const int*)d_in[9];
    float* out = (float*)d_out;

    int n = in_sizes[0] / CH;                 // 200000
    int M = in_sizes[8] / (PATHS * KOFF);     // max pairs per (p,k)

    size_t total4 = (size_t)n * CH / 4;
    int zb = (int)((total4 + 255) / 256);
    zero_init<<<zb, 256>>>(total4);
    gemm_h<<<dim3(PATHS, (n + 127) / 128), 256>>>(x, Wl, bl, n);
    conv_scatter<<<dim3((M + 127) / 128, KOFF, PATHS), 256>>>(Wc, in_idx, out_idx, n, M);
    bn_stats<<<512, 256>>>(n);
    bn_finalize<<<1, 256>>>(gamma, beta, n);
    gemm_out<<<dim3(PATHS, (n + 127) / 128), 256>>>(W2, b2, x, out, n);
}

// round 3
// speedup vs baseline: 2.1776x; 1.2901x over previous
#include <cuda_runtime.h>
#include <cstdint>

#define CH 256
#define NMAX 200000
#define KOFF 27
#define PATHS 4

// Scratch (device globals: no allocation allowed in kernel_launch)
__device__ float g_H[(size_t)NMAX * CH];     // lifted features, pre-rounded tf32
__device__ float g_A[(size_t)NMAX * CH];     // conv accumulator (fp32)
__device__ float g_sum[CH];
__device__ float g_sumsq[CH];
__device__ float g_scale[CH];
__device__ float g_shift[CH];
__device__ float g_Wlr[65536];               // Wl permuted to [k][n], tf32-rounded
__device__ float g_W2r[65536];               // W2 [k][n], tf32-rounded
__device__ float g_Wcr[442368];              // Wc same layout, tf32-rounded

// ---------------------------------------------------------------------------
__device__ __forceinline__ float to_tf32(float f) {
    uint32_t u;
    asm("cvt.rna.tf32.f32 %0, %1;" : "=r"(u) : "f"(f));
    return __uint_as_float(u);
}

__device__ __forceinline__ void mma_tf32(float c[4], uint32_t a0, uint32_t a1,
                                         uint32_t a2, uint32_t a3,
                                         uint32_t b0, uint32_t b1) {
    asm volatile(
        "mma.sync.aligned.m16n8k8.row.col.f32.tf32.tf32.f32 "
        "{%0,%1,%2,%3}, {%4,%5,%6,%7}, {%8,%9}, {%0,%1,%2,%3};\n"
        : "+f"(c[0]), "+f"(c[1]), "+f"(c[2]), "+f"(c[3])
        : "r"(a0), "r"(a1), "r"(a2), "r"(a3), "r"(b0), "r"(b1));
}

__device__ __forceinline__ uint32_t smem_u32(const void* p) {
    return (uint32_t)__cvta_generic_to_shared(p);
}
__device__ __forceinline__ void cp16(uint32_t dst, const void* src, int sz) {
    asm volatile("cp.async.cg.shared.global [%0], [%1], 16, %2;"
                 :: "r"(dst), "l"(src), "r"(sz));
}
__device__ __forceinline__ void cp_commit() { asm volatile("cp.async.commit_group;"); }
template <int N> __device__ __forceinline__ void cp_wait() {
    asm volatile("cp.async.wait_group %0;" :: "n"(N));
}
__device__ __forceinline__ void red_v4(float* dst, float4 v) {
    asm volatile("red.global.add.v4.f32 [%0], {%1,%2,%3,%4};"
                 :: "l"(dst), "f"(v.x), "f"(v.y), "f"(v.z), "f"(v.w) : "memory");
}

// ---------------------------------------------------------------------------
// Round weights to tf32 once (Wl also permuted [P][k][d] -> [k][p*64+d])
__global__ void prep_weights(const float* __restrict__ Wl,
                             const float* __restrict__ W2,
                             const float* __restrict__ Wc) {
    int i = blockIdx.x * 256 + threadIdx.x;
    if (i < 65536) {
        int p = i >> 14, k = (i >> 6) & 255, d = i & 63;
        g_Wlr[k * 256 + p * 64 + d] = to_tf32(Wl[i]);
    } else if (i < 131072) {
        int j = i - 65536;
        g_W2r[j] = to_tf32(W2[j]);
    } else if (i < 131072 + 442368) {
        int j = i - 131072;
        g_Wcr[j] = to_tf32(Wc[j]);
    }
}

// ---------------------------------------------------------------------------
__global__ void zero_init(size_t total4) {
    size_t i = (size_t)blockIdx.x * blockDim.x + threadIdx.x;
    if (i < total4) ((float4*)g_A)[i] = make_float4(0.f, 0.f, 0.f, 0.f);
    if (i < CH) { g_sum[i] = 0.f; g_sumsq[i] = 0.f; }
}

// ---------------------------------------------------------------------------
// H = tf32round(x @ Wl_cat + bl).  Tile 128x128, BK=16, 2-stage cp.async pipeline.
__global__ __launch_bounds__(256) void gemm_h(const float* __restrict__ x,
                                              const float* __restrict__ bl, int n) {
    __shared__ float As[2][128][20];
    __shared__ float Bs[2][16][136];
    const int colBase = blockIdx.x * 128;
    const int rowBase = blockIdx.y * 128;
    const int tid = threadIdx.x;
    const int warpId = tid >> 5, lane = tid & 31;
    const int grp = lane >> 2, qp = lane & 3;
    const int wm = (warpId & 3) * 32, wn = (warpId >> 2) * 64;

    float acc[2][8][4];
#pragma unroll
    for (int mt = 0; mt < 2; mt++)
#pragma unroll
        for (int nt = 0; nt < 8; nt++)
#pragma unroll
            for (int r = 0; r < 4; r++) acc[mt][nt][r] = 0.f;

    float4 ar[2];
    int arow[2], akq[2];
#pragma unroll
    for (int i = 0; i < 2; i++) { int ci = tid + i * 256; arow[i] = ci >> 2; akq[i] = ci & 3; }

#define LOAD_A(kt) do {                                                        \
    _Pragma("unroll")                                                          \
    for (int i = 0; i < 2; i++) {                                              \
        int gr = rowBase + arow[i];                                            \
        ar[i] = (gr < n) ? *(const float4*)&x[(size_t)gr * CH + (kt) * 16 + akq[i] * 4] \
                         : make_float4(0.f, 0.f, 0.f, 0.f);                    \
    } } while (0)
#define STS_A(b) do {                                                          \
    _Pragma("unroll")                                                          \
    for (int i = 0; i < 2; i++) {                                              \
        float4 v = ar[i];                                                      \
        v.x = to_tf32(v.x); v.y = to_tf32(v.y); v.z = to_tf32(v.z); v.w = to_tf32(v.w); \
        *(float4*)&As[b][arow[i]][akq[i] * 4] = v;                             \
    } } while (0)
#define LOAD_B(kt, b) do {                                                     \
    _Pragma("unroll")                                                          \
    for (int i = 0; i < 2; i++) {                                              \
        int ci = tid + i * 256; int kk = ci >> 5, nc = ci & 31;                \
        cp16(smem_u32(&Bs[b][kk][nc * 4]),                                     \
             &g_Wlr[(size_t)((kt) * 16 + kk) * 256 + colBase + nc * 4], 16);   \
    }                                                                          \
    cp_commit(); } while (0)
#define COMPUTE(b) do {                                                        \
    _Pragma("unroll")                                                          \
    for (int c8 = 0; c8 < 2; c8++) {                                           \
        int kk0 = c8 * 8;                                                      \
        uint32_t af[2][4], bf[8][2];                                           \
        _Pragma("unroll")                                                      \
        for (int mt = 0; mt < 2; mt++) {                                       \
            int r0 = wm + mt * 16 + grp;                                       \
            af[mt][0] = __float_as_uint(As[b][r0][kk0 + qp]);                  \
            af[mt][1] = __float_as_uint(As[b][r0 + 8][kk0 + qp]);              \
            af[mt][2] = __float_as_uint(As[b][r0][kk0 + qp + 4]);              \
            af[mt][3] = __float_as_uint(As[b][r0 + 8][kk0 + qp + 4]);          \
        }                                                                      \
        _Pragma("unroll")                                                      \
        for (int nt = 0; nt < 8; nt++) {                                       \
            int c0 = wn + nt * 8 + grp;                                        \
            bf[nt][0] = __float_as_uint(Bs[b][kk0 + qp][c0]);                  \
            bf[nt][1] = __float_as_uint(Bs[b][kk0 + qp + 4][c0]);              \
        }                                                                      \
        _Pragma("unroll")                                                      \
        for (int mt = 0; mt < 2; mt++)                                         \
            _Pragma("unroll")                                                  \
            for (int nt = 0; nt < 8; nt++)                                     \
                mma_tf32(acc[mt][nt], af[mt][0], af[mt][1], af[mt][2], af[mt][3], \
                         bf[nt][0], bf[nt][1]);                                \
    } } while (0)

    LOAD_B(0, 0);
    LOAD_B(1, 1);
    LOAD_A(0); STS_A(0); LOAD_A(1);
    cp_wait<1>(); __syncthreads();
    for (int kt = 0; kt < 16; kt++) {
        int b = kt & 1;
        if (kt + 1 < 16) STS_A(b ^ 1);
        if (kt + 2 < 16) LOAD_A(kt + 2);
        COMPUTE(b);
        if (kt + 1 < 16) cp_wait<0>();
        __syncthreads();
        if (kt + 2 < 16) LOAD_B(kt + 2, b);
    }
#undef LOAD_A
#undef STS_A
#undef LOAD_B
#undef COMPUTE

#pragma unroll
    for (int mt = 0; mt < 2; mt++) {
#pragma unroll
        for (int nt = 0; nt < 8; nt++) {
            int col = colBase + wn + nt * 8 + qp * 2;
            float b0 = bl[col], b1 = bl[col + 1];
            int gr0 = rowBase + wm + mt * 16 + grp;
            if (gr0 < n) {
                float2 o = make_float2(to_tf32(acc[mt][nt][0] + b0),
                                       to_tf32(acc[mt][nt][1] + b1));
                *(float2*)&g_H[(size_t)gr0 * CH + col] = o;
            }
            int gr1 = gr0 + 8;
            if (gr1 < n) {
                float2 o = make_float2(to_tf32(acc[mt][nt][2] + b0),
                                       to_tf32(acc[mt][nt][3] + b1));
                *(float2*)&g_H[(size_t)gr1 * CH + col] = o;
            }
        }
    }
}

// ---------------------------------------------------------------------------
// Sparse conv: 128-pair tile, cp.async gather (XOR-swizzled), tf32 mma,
// SMEM-staged epilogue with red.global.add.v4.f32 scatter.
__global__ __launch_bounds__(256) void conv_scatter(const int* __restrict__ in_idx,
                                                    const int* __restrict__ out_idx,
                                                    int n, int M) {
    __shared__ float Gs[128][64];   // swizzled: (m,c) at col c ^ ((m&7)<<2)
    __shared__ float Ws[64][64];    // swizzled: (k,c) at col c ^ ((k&3)<<3)
    int p = blockIdx.z, k = blockIdx.y;
    size_t base = (size_t)(p * KOFF + k) * M + (size_t)blockIdx.x * 128;
    const int* ii = in_idx + base;
    if (__ldg(ii) >= n) return;     // whole tile is sentinel padding
    int rem = M - blockIdx.x * 128; if (rem > 128) rem = 128;
    int tid = threadIdx.x;

    const float* Wpk = g_Wcr + (size_t)(p * KOFF + k) * 4096;
#pragma unroll
    for (int i = 0; i < 4; i++) {
        int ci = tid + i * 256;
        int c = ci >> 4, q = ci & 15;
        int csw = (q * 4) ^ ((c & 3) << 3);
        cp16(smem_u32(&Ws[c][csw]), &Wpk[c * 64 + q * 4], 16);
    }
    {
        int m = tid >> 1, half = tid & 1;
        int jm = (m < rem) ? __ldg(&ii[m]) : n;
        int sz = (jm < n) ? 16 : 0;
        const float* hp = &g_H[(size_t)(jm < n ? jm : 0) * CH + p * 64 + half * 32];
#pragma unroll
        for (int q = 0; q < 8; q++) {
            int cb = half * 32 + q * 4;
            int csw = cb ^ ((m & 7) << 2);
            cp16(smem_u32(&Gs[m][csw]), hp + q * 4, sz);
        }
    }
    cp_commit(); cp_wait<0>(); __syncthreads();

    int warpId = tid >> 5, lane = tid & 31;
    int grp = lane >> 2, qp = lane & 3;
    int wm = (warpId & 3) * 32, wn = (warpId >> 2) * 32;
    float acc[2][4][4];
#pragma unroll
    for (int mt = 0; mt < 2; mt++)
#pragma unroll
        for (int nt = 0; nt < 4; nt++)
#pragma unroll
            for (int r = 0; r < 4; r++) acc[mt][nt][r] = 0.f;

#pragma unroll
    for (int c8 = 0; c8 < 8; c8++) {
        int kk0 = c8 * 8;
        uint32_t af[2][4], bf[4][2];
        int sx = grp << 2;
#pragma unroll
        for (int mt = 0; mt < 2; mt++) {
            int r0 = wm + mt * 16 + grp;
            af[mt][0] = __float_as_uint(Gs[r0][(kk0 + qp) ^ sx]);
            af[mt][1] = __float_as_uint(Gs[r0 + 8][(kk0 + qp) ^ sx]);
            af[mt][2] = __float_as_uint(Gs[r0][(kk0 + qp + 4) ^ sx]);
            af[mt][3] = __float_as_uint(Gs[r0 + 8][(kk0 + qp + 4) ^ sx]);
        }
#pragma unroll
        for (int nt = 0; nt < 4; nt++) {
            int c0 = wn + nt * 8 + grp;
            bf[nt][0] = __float_as_uint(Ws[kk0 + qp][c0 ^ (qp << 3)]);
            bf[nt][1] = __float_as_uint(Ws[kk0 + qp + 4][c0 ^ (qp << 3)]);
        }
#pragma unroll
        for (int mt = 0; mt < 2; mt++)
#pragma unroll
            for (int nt = 0; nt < 4; nt++)
                mma_tf32(acc[mt][nt], af[mt][0], af[mt][1], af[mt][2], af[mt][3],
                         bf[nt][0], bf[nt][1]);
    }

    __syncthreads();                 // all warps done reading Gs
    // Stage results (plain layout) for vectorized scatter
#pragma unroll
    for (int mt = 0; mt < 2; mt++)
#pragma unroll
        for (int nt = 0; nt < 4; nt++) {
            int col = wn + nt * 8 + qp * 2;
            int r0 = wm + mt * 16 + grp;
            *(float2*)&Gs[r0][col]     = make_float2(acc[mt][nt][0], acc[mt][nt][1]);
            *(float2*)&Gs[r0 + 8][col] = make_float2(acc[mt][nt][2], acc[mt][nt][3]);
        }
    __syncthreads();

#pragma unroll
    for (int i = 0; i < 8; i++) {
        int idx = tid + i * 256;
        int row = idx >> 4, c4 = idx & 15;
        int o = (row < rem) ? __ldg(&out_idx[base + row]) : n;
        if (o < n) {
            float4 v = *(const float4*)&Gs[row][c4 * 4];
            red_v4(&g_A[(size_t)o * CH + p * 64 + c4 * 4], v);
        }
    }
}

// ---------------------------------------------------------------------------
__global__ __launch_bounds__(256) void bn_stats(int n) {
    __shared__ float4 rs[4][64], rq[4][64];
    int tid = threadIdx.x;
    int cq = tid & 63;
    int rl = tid >> 6;
    float4 s = make_float4(0.f, 0.f, 0.f, 0.f);
    float4 s2 = make_float4(0.f, 0.f, 0.f, 0.f);
#pragma unroll 8
    for (int r = blockIdx.x * 4 + rl; r < n; r += gridDim.x * 4) {
        float4 v = *(const float4*)&g_A[(size_t)r * CH + cq * 4];
        s.x += v.x; s.y += v.y; s.z += v.z; s.w += v.w;
        s2.x += v.x * v.x; s2.y += v.y * v.y; s2.z += v.z * v.z; s2.w += v.w * v.w;
    }
    rs[rl][cq] = s; rq[rl][cq] = s2;
    __syncthreads();
    if (rl == 0) {
#pragma unroll
        for (int i = 1; i < 4; i++) {
            float4 a = rs[i][cq], b = rq[i][cq];
            s.x += a.x; s.y += a.y; s.z += a.z; s.w += a.w;
            s2.x += b.x; s2.y += b.y; s2.z += b.z; s2.w += b.w;
        }
        int c = cq * 4;
        atomicAdd(&g_sum[c + 0], s.x);  atomicAdd(&g_sum[c + 1], s.y);
        atomicAdd(&g_sum[c + 2], s.z);  atomicAdd(&g_sum[c + 3], s.w);
        atomicAdd(&g_sumsq[c + 0], s2.x); atomicAdd(&g_sumsq[c + 1], s2.y);
        atomicAdd(&g_sumsq[c + 2], s2.z); atomicAdd(&g_sumsq[c + 3], s2.w);
    }
}

__global__ void bn_finalize(const float* __restrict__ gamma,
                            const float* __restrict__ beta, int n) {
    int j = threadIdx.x;
    float inv = 1.f / (float)n;
    float mu = g_sum[j] * inv;
    float var = g_sumsq[j] * inv - mu * mu;
    float sc = gamma[j] * rsqrtf(var + 1e-5f);
    g_scale[j] = sc;
    g_shift[j] = beta[j] - mu * sc;
}

// ---------------------------------------------------------------------------
// out = relu(bn(A)) @ W2 + b2 + x.  Same pipelined skeleton as gemm_h.
__global__ __launch_bounds__(256) void gemm_out(const float* __restrict__ b2,
                                                const float* __restrict__ x,
                                                float* __restrict__ out, int n) {
    __shared__ float As[2][128][20];
    __shared__ float Bs[2][16][136];
    __shared__ float sc[256], sh[256];
    const int colBase = blockIdx.x * 128;
    const int rowBase = blockIdx.y * 128;
    const int tid = threadIdx.x;
    const int warpId = tid >> 5, lane = tid & 31;
    const int grp = lane >> 2, qp = lane & 3;
    const int wm = (warpId & 3) * 32, wn = (warpId >> 2) * 64;

    sc[tid] = g_scale[tid];
    sh[tid] = g_shift[tid];

    float acc[2][8][4];
#pragma unroll
    for (int mt = 0; mt < 2; mt++)
#pragma unroll
        for (int nt = 0; nt < 8; nt++)
#pragma unroll
            for (int r = 0; r < 4; r++) acc[mt][nt][r] = 0.f;

    float4 ar[2];
    int arow[2], akq[2];
#pragma unroll
    for (int i = 0; i < 2; i++) { int ci = tid + i * 256; arow[i] = ci >> 2; akq[i] = ci & 3; }

#define LOAD_A(kt) do {                                                        \
    _Pragma("unroll")                                                          \
    for (int i = 0; i < 2; i++) {                                              \
        int gr = rowBase + arow[i];                                            \
        ar[i] = (gr < n) ? *(const float4*)&g_A[(size_t)gr * CH + (kt) * 16 + akq[i] * 4] \
                         : make_float4(0.f, 0.f, 0.f, 0.f);                    \
    } } while (0)
#define STS_A(b, kt) do {                                                      \
    _Pragma("unroll")                                                          \
    for (int i = 0; i < 2; i++) {                                              \
        float4 v = ar[i];                                                      \
        int c0 = (kt) * 16 + akq[i] * 4;                                       \
        v.x = to_tf32(fmaxf(v.x * sc[c0 + 0] + sh[c0 + 0], 0.f));              \
        v.y = to_tf32(fmaxf(v.y * sc[c0 + 1] + sh[c0 + 1], 0.f));              \
        v.z = to_tf32(fmaxf(v.z * sc[c0 + 2] + sh[c0 + 2], 0.f));              \
        v.w = to_tf32(fmaxf(v.w * sc[c0 + 3] + sh[c0 + 3], 0.f));              \
        *(float4*)&As[b][arow[i]][akq[i] * 4] = v;                             \
    } } while (0)
#define LOAD_B(kt, b) do {                                                     \
    _Pragma("unroll")                                                          \
    for (int i = 0; i < 2; i++) {                                              \
        int ci = tid + i * 256; int kk = ci >> 5, nc = ci & 31;                \
        cp16(smem_u32(&Bs[b][kk][nc * 4]),                                     \
             &g_W2r[(size_t)((kt) * 16 + kk) * 256 + colBase + nc * 4], 16);   \
    }                                                                          \
    cp_commit(); } while (0)
#define COMPUTE(b) do {                                                        \
    _Pragma("unroll")                                                          \
    for (int c8 = 0; c8 < 2; c8++) {                                           \
        int kk0 = c8 * 8;                                                      \
        uint32_t af[2][4], bf[8][2];                                           \
        _Pragma("unroll")                                                      \
        for (int mt = 0; mt < 2; mt++) {                                       \
            int r0 = wm + mt * 16 + grp;                                       \
            af[mt][0] = __float_as_uint(As[b][r0][kk0 + qp]);                  \
            af[mt][1] = __float_as_uint(As[b][r0 + 8][kk0 + qp]);              \
            af[mt][2] = __float_as_uint(As[b][r0][kk0 + qp + 4]);              \
            af[mt][3] = __float_as_uint(As[b][r0 + 8][kk0 + qp + 4]);          \
        }                                                                      \
        _Pragma("unroll")                                                      \
        for (int nt = 0; nt < 8; nt++) {                                       \
            int c0 = wn + nt * 8 + grp;                                        \
            bf[nt][0] = __float_as_uint(Bs[b][kk0 + qp][c0]);                  \
            bf[nt][1] = __float_as_uint(Bs[b][kk0 + qp + 4][c0]);              \
        }                                                                      \
        _Pragma("unroll")                                                      \
        for (int mt = 0; mt < 2; mt++)                                         \
            _Pragma("unroll")                                                  \
            for (int nt = 0; nt < 8; nt++)                                     \
                mma_tf32(acc[mt][nt], af[mt][0], af[mt][1], af[mt][2], af[mt][3], \
                         bf[nt][0], bf[nt][1]);                                \
    } } while (0)

    LOAD_B(0, 0);
    LOAD_B(1, 1);
    LOAD_A(0);
    __syncthreads();                 // publish sc/sh before STS_A uses them
    STS_A(0, 0); LOAD_A(1);
    cp_wait<1>(); __syncthreads();
    for (int kt = 0; kt < 16; kt++) {
        int b = kt & 1;
        if (kt + 1 < 16) STS_A(b ^ 1, kt + 1);
        if (kt + 2 < 16) LOAD_A(kt + 2);
        COMPUTE(b);
        if (kt + 1 < 16) cp_wait<0>();
        __syncthreads();
        if (kt + 2 < 16) LOAD_B(kt + 2, b);
    }
#undef LOAD_A
#undef STS_A
#undef LOAD_B
#undef COMPUTE

#pragma unroll
    for (int mt = 0; mt < 2; mt++) {
#pragma unroll
        for (int nt = 0; nt < 8; nt++) {
            int col = colBase + wn + nt * 8 + qp * 2;
            float b0 = b2[col], b1 = b2[col + 1];
            int gr0 = rowBase + wm + mt * 16 + grp;
            if (gr0 < n) {
                float2 xr = *(const float2*)&x[(size_t)gr0 * CH + col];
                *(float2*)&out[(size_t)gr0 * CH + col] =
                    make_float2(acc[mt][nt][0] + b0 + xr.x, acc[mt][nt][1] + b1 + xr.y);
            }
            int gr1 = gr0 + 8;
            if (gr1 < n) {
                float2 xr = *(const float2*)&x[(size_t)gr1 * CH + col];
                *(float2*)&out[(size_t)gr1 * CH + col] =
                    make_float2(acc[mt][nt][2] + b0 + xr.x, acc[mt][nt][3] + b1 + xr.y);
            }
        }
    }
}

// ---------------------------------------------------------------------------
extern "C" void kernel_launch(void* const* d_in, const int* in_sizes, int n_in,
                              void* d_out, int out_size) {
    const float* x     = (const float*)d_in[0];
    const float* Wl    = (const float*)d_in[1];
    const float* bl    = (const float*)d_in[2];
    const float* Wc    = (const float*)d_in[3];
    const float* gamma = (const float*)d_in[4];
    const float* beta  = (const float*)d_in[5];
    const float* W2    = (const float*)d_in[6];
    const float* b2    = (const float*)d_in[7];
    const int* in_idx  = (const int*)d_in[8];
    const int* out_idx = (const int*)d_in[9];
    float* out = (float*)d_out;

    int n = in_sizes[0] / CH;                 // 200000
    int M = in_sizes[8] / (PATHS * KOFF);     // max pairs per (p,k)

    prep_weights<<<2240, 256>>>(Wl, W2, Wc);
    size_t total4 = (size_t)n * CH / 4;
    int zb = (int)((total4 + 255) / 256);
    zero_init<<<zb, 256>>>(total4);
    gemm_h<<<dim3(2, (n + 127) / 128), 256>>>(x, bl, n);
    conv_scatter<<<dim3((M + 127) / 128, KOFF, PATHS), 256>>>(in_idx, out_idx, n, M);
    bn_stats<<<1536, 256>>>(n);
    bn_finalize<<<1, 256>>>(gamma, beta, n);
    gemm_out<<<dim3(2, (n + 127) / 128), 256>>>(b2, x, out, n);
}